// round 3
// baseline (speedup 1.0000x reference)
#include <cuda_runtime.h>
#include <cuda_bf16.h>
#include <stdint.h>

// ---------------- problem constants ----------------
#define NATOMS   16384
#define NSEL     4096
#define NODE_F   8
#define HID      128
#define HEADS    8
#define DH       16
#define OUTD     256
#define NLIG     32
#define NBINS    65536

typedef unsigned long long ull;

// ---------------- scratch (static device memory; no allocation) ----------------
__device__ float    g_center[3];
__device__ float    g_sq[NATOMS];
__device__ float    g_s0[NATOMS];
__device__ int      g_cnt[NATOMS];
__device__ unsigned g_keys[NATOMS];
__device__ unsigned g_hist[NBINS];
__device__ int      g_H;
__device__ int      g_r;
__device__ int      g_m;
__device__ ull      g_bbuf[NATOMS];
__device__ int      g_sel[NATOMS];
__device__ int      g_bsum[64];
__device__ int      g_boff[64];
__device__ int      g_idx[NSEL];
__device__ float    g_q[NSEL * HID];
__device__ float    g_k[NSEL * HID];
__device__ float    g_v[NSEL * HID];
__device__ float    g_av[NSEL * HID];
__device__ float    g_mav[HID];

// ---------------- 0: zero scratch that is accumulated into ----------------
__global__ void k_zero() {
    int i = blockIdx.x * blockDim.x + threadIdx.x;
    if (i < NBINS) g_hist[i] = 0;
    else if (i < NBINS + NATOMS) g_cnt[i - NBINS] = 0;
    if (i == 0) g_m = 0;
}

// ---------------- 1: ligand center ----------------
__global__ void k_center(const float* __restrict__ lig) {
    int t = threadIdx.x;  // 32 threads
    float x = lig[t * 3 + 0], y = lig[t * 3 + 1], z = lig[t * 3 + 2];
    #pragma unroll
    for (int o = 16; o > 0; o >>= 1) {
        x += __shfl_down_sync(0xFFFFFFFFu, x, o);
        y += __shfl_down_sync(0xFFFFFFFFu, y, o);
        z += __shfl_down_sync(0xFFFFFFFFu, z, o);
    }
    if (t == 0) {
        g_center[0] = x * (1.0f / NLIG);
        g_center[1] = y * (1.0f / NLIG);
        g_center[2] = z * (1.0f / NLIG);
    }
}

// ---------------- 2: per-atom sq norm + ligand-distance score term ----------------
__global__ void k_base(const float* __restrict__ pos) {
    int i = blockIdx.x * blockDim.x + threadIdx.x;
    if (i >= NATOMS) return;
    float x = pos[i * 3 + 0], y = pos[i * 3 + 1], z = pos[i * 3 + 2];
    g_sq[i] = fmaf(z, z, fmaf(y, y, x * x));
    float dx = x - g_center[0], dy = y - g_center[1], dz = z - g_center[2];
    float d = sqrtf(fmaf(dz, dz, fmaf(dy, dy, dx * dx)));
    g_s0[i] = 1.0f / (1.0f + d / 5.0f);
}

// ---------------- 3: brute-force neighbor counting (d2 = sqi+sqj-2*dot < 9) ----------------
__global__ __launch_bounds__(256) void k_neighbor(const float* __restrict__ pos) {
    __shared__ float4 tile[256];
    int tid = threadIdx.x;
    int i = blockIdx.x * 256 + tid;
    float px = pos[i * 3 + 0], py = pos[i * 3 + 1], pz = pos[i * 3 + 2];
    float si = g_sq[i];
    int cnt = 0;
    int j0 = blockIdx.y * 2048;
    for (int jt = 0; jt < 8; jt++) {
        int j = j0 + jt * 256 + tid;
        tile[tid] = make_float4(pos[j * 3 + 0], pos[j * 3 + 1], pos[j * 3 + 2], g_sq[j]);
        __syncthreads();
        #pragma unroll 8
        for (int jj = 0; jj < 256; jj++) {
            float4 T = tile[jj];
            float dot = fmaf(pz, T.z, fmaf(py, T.y, px * T.x));
            float d2  = fmaf(-2.0f, dot, si + T.w);
            cnt += (d2 < 9.0f);
        }
        __syncthreads();
    }
    atomicAdd(&g_cnt[i], cnt);  // integer: deterministic
}

// ---------------- 4: final scores -> sortable keys + histogram ----------------
__global__ void k_scorekey() {
    int i = blockIdx.x * blockDim.x + threadIdx.x;
    if (i >= NATOMS) return;
    // count includes self; neighbor_counts = cnt-1; surface = 1/(nc+1) = 1/cnt
    float surface = 1.0f / (float)g_cnt[i];
    float s = g_s0[i] + 0.5f * surface;          // strictly positive
    unsigned key = __float_as_uint(s);           // monotone for positive floats
    g_keys[i] = key;
    atomicAdd(&g_hist[key >> 16], 1u);
}

// ---------------- 5: find threshold bin H and count r needed from it ----------------
__global__ void k_scan() {
    __shared__ unsigned csum[256];
    int t = threadIdx.x;
    unsigned s = 0;
    for (int b = t * 256; b < (t + 1) * 256; b++) s += g_hist[b];
    csum[t] = s;
    __syncthreads();
    if (t == 0) {
        unsigned g = 0;
        int chunk = 255;
        for (; chunk > 0; chunk--) {
            if (g + csum[chunk] >= (unsigned)NSEL) break;
            g += csum[chunk];
        }
        int H = chunk * 256;
        unsigned r = 1;
        for (int b = chunk * 256 + 255; b >= chunk * 256; b--) {
            unsigned c = g_hist[b];
            if (g + c >= (unsigned)NSEL) { H = b; r = (unsigned)NSEL - g; break; }
            g += c;
        }
        g_H = H;
        g_r = (int)r;
    }
}

// ---------------- 6: collect boundary-bin elements ----------------
__global__ void k_boundary() {
    int i = blockIdx.x * blockDim.x + threadIdx.x;
    if (i >= NATOMS) return;
    unsigned key = g_keys[i];
    if ((int)(key >> 16) == g_H) {
        int p = atomicAdd(&g_m, 1);
        // priority: higher score first, then lower index first
        g_bbuf[p] = ((ull)key << 32) | (ull)(0xFFFFFFFFu - (unsigned)i);
    }
}

// ---------------- 7: selection flags (exact top-k semantics incl. ties) ----------------
__global__ void k_flags() {
    int i = blockIdx.x * blockDim.x + threadIdx.x;
    if (i >= NATOMS) return;
    unsigned key = g_keys[i];
    int hi = (int)(key >> 16);
    int s = 0;
    if (hi > g_H) s = 1;
    else if (hi == g_H) {
        ull mine = ((ull)key << 32) | (ull)(0xFFFFFFFFu - (unsigned)i);
        int m = g_m, cnt = 0, r = g_r;
        for (int t = 0; t < m; t++) cnt += (g_bbuf[t] > mine);
        if (cnt < r) s = 1;
    }
    g_sel[i] = s;
}

// ---------------- 8: deterministic compaction (3 passes) ----------------
__global__ void k_bcount() {
    __shared__ int sm[256];
    int t = threadIdx.x;
    sm[t] = g_sel[blockIdx.x * 256 + t];
    __syncthreads();
    for (int o = 128; o > 0; o >>= 1) {
        if (t < o) sm[t] += sm[t + o];
        __syncthreads();
    }
    if (t == 0) g_bsum[blockIdx.x] = sm[0];
}
__global__ void k_boffsets() {
    if (threadIdx.x == 0) {
        int acc = 0;
        for (int b = 0; b < 64; b++) { g_boff[b] = acc; acc += g_bsum[b]; }
    }
}
__global__ void k_compact() {
    __shared__ int sc[256];
    int t = threadIdx.x;
    int i = blockIdx.x * 256 + t;
    int f = g_sel[i];
    sc[t] = f;
    __syncthreads();
    for (int o = 1; o < 256; o <<= 1) {
        int v = (t >= o) ? sc[t - o] : 0;
        __syncthreads();
        sc[t] += v;
        __syncthreads();
    }
    if (f) g_idx[g_boff[blockIdx.x] + sc[t] - 1] = i;
}

// ---------------- 9: fused gather + node-embed + QKV projection ----------------
__global__ __launch_bounds__(128) void k_qkv(
    const float* __restrict__ x,
    const float* __restrict__ Wn, const float* __restrict__ bn,
    const float* __restrict__ Wq, const float* __restrict__ bq,
    const float* __restrict__ Wk, const float* __restrict__ bk,
    const float* __restrict__ Wv, const float* __restrict__ bv)
{
    __shared__ float hs[4][HID];
    int c = threadIdx.x;
    int r0 = blockIdx.x * 4;
    #pragma unroll
    for (int rr = 0; rr < 4; rr++) {
        int row = g_idx[r0 + rr];
        const float* xr = x + row * NODE_F;
        float acc = bn[c];
        #pragma unroll
        for (int f = 0; f < NODE_F; f++) acc = fmaf(__ldg(xr + f), Wn[f * HID + c], acc);
        hs[rr][c] = acc;
    }
    __syncthreads();
    float aq[4], ak[4], av[4];
    #pragma unroll
    for (int rr = 0; rr < 4; rr++) { aq[rr] = bq[c]; ak[rr] = bk[c]; av[rr] = bv[c]; }
    for (int d = 0; d < HID; d++) {
        float wq = Wq[d * HID + c], wk = Wk[d * HID + c], wv = Wv[d * HID + c];
        #pragma unroll
        for (int rr = 0; rr < 4; rr++) {
            float h = hs[rr][d];
            aq[rr] = fmaf(h, wq, aq[rr]);
            ak[rr] = fmaf(h, wk, ak[rr]);
            av[rr] = fmaf(h, wv, av[rr]);
        }
    }
    #pragma unroll
    for (int rr = 0; rr < 4; rr++) {
        g_q[(r0 + rr) * HID + c] = aq[rr];
        g_k[(r0 + rr) * HID + c] = ak[rr];
        g_v[(r0 + rr) * HID + c] = av[rr];
    }
}

// ---------------- 10: flash-style attention, fp32, no max-subtraction ----------------
// logits ~ N(0,1): exp() cannot overflow fp32; softmax = sum(exp*v)/sum(exp).
__global__ __launch_bounds__(128) void k_attn() {
    __shared__ float4 Ks[128][4];
    __shared__ float4 Vs[128][4];
    int h = blockIdx.y;
    int tid = threadIdx.x;
    int qi = blockIdx.x * 128 + tid;

    const float scale = 0.25f;  // 1/sqrt(16)
    float qv[DH];
    #pragma unroll
    for (int d = 0; d < DH; d++) qv[d] = g_q[qi * HID + h * DH + d] * scale;

    float o[DH];
    #pragma unroll
    for (int d = 0; d < DH; d++) o[d] = 0.0f;
    float l = 0.0f;

    for (int kt = 0; kt < NSEL / 128; kt++) {
        int kr = kt * 128 + tid;
        const float4* kp = (const float4*)&g_k[kr * HID + h * DH];
        const float4* vp = (const float4*)&g_v[kr * HID + h * DH];
        Ks[tid][0] = kp[0]; Ks[tid][1] = kp[1]; Ks[tid][2] = kp[2]; Ks[tid][3] = kp[3];
        Vs[tid][0] = vp[0]; Vs[tid][1] = vp[1]; Vs[tid][2] = vp[2]; Vs[tid][3] = vp[3];
        __syncthreads();
        #pragma unroll 4
        for (int j = 0; j < 128; j++) {
            float4 a = Ks[j][0], b = Ks[j][1], c = Ks[j][2], d4 = Ks[j][3];
            float s;
            s = qv[0] * a.x;
            s = fmaf(qv[1],  a.y, s); s = fmaf(qv[2],  a.z, s); s = fmaf(qv[3],  a.w, s);
            s = fmaf(qv[4],  b.x, s); s = fmaf(qv[5],  b.y, s); s = fmaf(qv[6],  b.z, s);
            s = fmaf(qv[7],  b.w, s); s = fmaf(qv[8],  c.x, s); s = fmaf(qv[9],  c.y, s);
            s = fmaf(qv[10], c.z, s); s = fmaf(qv[11], c.w, s); s = fmaf(qv[12], d4.x, s);
            s = fmaf(qv[13], d4.y, s); s = fmaf(qv[14], d4.z, s); s = fmaf(qv[15], d4.w, s);
            float p = __expf(s);
            l += p;
            float4 va = Vs[j][0], vb = Vs[j][1], vc = Vs[j][2], vd = Vs[j][3];
            o[0]  = fmaf(p, va.x, o[0]);  o[1]  = fmaf(p, va.y, o[1]);
            o[2]  = fmaf(p, va.z, o[2]);  o[3]  = fmaf(p, va.w, o[3]);
            o[4]  = fmaf(p, vb.x, o[4]);  o[5]  = fmaf(p, vb.y, o[5]);
            o[6]  = fmaf(p, vb.z, o[6]);  o[7]  = fmaf(p, vb.w, o[7]);
            o[8]  = fmaf(p, vc.x, o[8]);  o[9]  = fmaf(p, vc.y, o[9]);
            o[10] = fmaf(p, vc.z, o[10]); o[11] = fmaf(p, vc.w, o[11]);
            o[12] = fmaf(p, vd.x, o[12]); o[13] = fmaf(p, vd.y, o[13]);
            o[14] = fmaf(p, vd.z, o[14]); o[15] = fmaf(p, vd.w, o[15]);
        }
        __syncthreads();
    }
    float inv = 1.0f / l;
    #pragma unroll
    for (int d = 0; d < DH; d++) g_av[qi * HID + h * DH + d] = o[d] * inv;
}

// ---------------- 11: deterministic column mean of av ----------------
__global__ void k_colsum() {
    __shared__ float sm[256];
    int col = blockIdx.x;
    int t = threadIdx.x;
    float s = 0.0f;
    for (int r = t; r < NSEL; r += 256) s += g_av[r * HID + col];
    sm[t] = s;
    __syncthreads();
    for (int o = 128; o > 0; o >>= 1) {
        if (t < o) sm[t] += sm[t + o];
        __syncthreads();
    }
    if (t == 0) g_mav[col] = sm[0] * (1.0f / NSEL);
}

// ---------------- 12: Wo + mean-pool commuted + MLP head ----------------
__global__ void k_final(
    const float* __restrict__ Wo, const float* __restrict__ bo,
    const float* __restrict__ W1, const float* __restrict__ b1,
    const float* __restrict__ W2, const float* __restrict__ b2,
    float* __restrict__ out)
{
    __shared__ float mav[HID];
    __shared__ float pooled[HID];
    __shared__ float t1[OUTD];
    int t = threadIdx.x;  // 256 threads
    if (t < HID) mav[t] = g_mav[t];
    __syncthreads();
    if (t < HID) {
        float acc = bo[t];
        for (int d = 0; d < HID; d++) acc = fmaf(mav[d], Wo[d * HID + t], acc);
        pooled[t] = acc;
    }
    __syncthreads();
    {
        float acc = b1[t];
        for (int d = 0; d < HID; d++) acc = fmaf(pooled[d], W1[d * OUTD + t], acc);
        t1[t] = fmaxf(acc, 0.0f);
    }
    __syncthreads();
    {
        float acc = b2[t];
        for (int d = 0; d < OUTD; d++) acc = fmaf(t1[d], W2[d * OUTD + t], acc);
        out[t] = acc;
    }
}

// ---------------- launcher ----------------
extern "C" void kernel_launch(void* const* d_in, const int* in_sizes, int n_in,
                              void* d_out, int out_size)
{
    const float* x    = (const float*)d_in[0];
    const float* pos  = (const float*)d_in[1];
    const float* lig  = (const float*)d_in[2];
    const float* Wn   = (const float*)d_in[3];
    const float* bn   = (const float*)d_in[4];
    const float* Wq   = (const float*)d_in[5];
    const float* bq   = (const float*)d_in[6];
    const float* Wk   = (const float*)d_in[7];
    const float* bk   = (const float*)d_in[8];
    const float* Wv   = (const float*)d_in[9];
    const float* bv   = (const float*)d_in[10];
    const float* Wo   = (const float*)d_in[11];
    const float* bo   = (const float*)d_in[12];
    const float* W1   = (const float*)d_in[13];
    const float* b1   = (const float*)d_in[14];
    const float* W2   = (const float*)d_in[15];
    const float* b2   = (const float*)d_in[16];
    float* out = (float*)d_out;

    k_zero<<<(NBINS + NATOMS + 255) / 256, 256>>>();
    k_center<<<1, 32>>>(lig);
    k_base<<<NATOMS / 256, 256>>>(pos);
    k_neighbor<<<dim3(NATOMS / 256, 8), 256>>>(pos);
    k_scorekey<<<NATOMS / 256, 256>>>();
    k_scan<<<1, 256>>>();
    k_boundary<<<NATOMS / 256, 256>>>();
    k_flags<<<NATOMS / 256, 256>>>();
    k_bcount<<<64, 256>>>();
    k_boffsets<<<1, 32>>>();
    k_compact<<<64, 256>>>();
    k_qkv<<<NSEL / 4, 128>>>(x, Wn, bn, Wq, bq, Wk, bk, Wv, bv);
    k_attn<<<dim3(NSEL / 128, HEADS), 128>>>();
    k_colsum<<<HID, 256>>>();
    k_final<<<1, 256>>>(Wo, bo, W1, b1, W2, b2, out);
}

// round 4
// speedup vs baseline: 1.0001x; 1.0001x over previous
#include <cuda_runtime.h>
#include <cuda_bf16.h>
#include <stdint.h>

// ---------------- problem constants ----------------
#define NATOMS   16384
#define NSEL     4096
#define NODE_F   8
#define HID      128
#define HEADS    8
#define DH       16
#define OUTD     256
#define NLIG     32
#define NBINS    65536

typedef unsigned long long ull;

// ---------------- scratch (static device memory; no allocation) ----------------
__device__ float    g_center[3];
__device__ float    g_sq[NATOMS];
__device__ float    g_s0[NATOMS];
__device__ int      g_cnt[NATOMS];
__device__ unsigned g_keys[NATOMS];
__device__ unsigned g_hist[NBINS];
__device__ int      g_H;
__device__ int      g_r;
__device__ int      g_m;
__device__ ull      g_bbuf[NATOMS];
__device__ int      g_sel[NATOMS];
__device__ int      g_bsum[64];
__device__ int      g_boff[64];
__device__ int      g_idx[NSEL];
__device__ float    g_q[NSEL * HID];
__device__ float    g_k[NSEL * HID];
__device__ float    g_v[NSEL * HID];
__device__ float    g_av[NSEL * HID];
__device__ float    g_mav[HID];

// ---------------- 0: zero scratch that is accumulated into ----------------
__global__ void k_zero() {
    int i = blockIdx.x * blockDim.x + threadIdx.x;
    if (i < NBINS) g_hist[i] = 0;
    else if (i < NBINS + NATOMS) g_cnt[i - NBINS] = 0;
    if (i == 0) g_m = 0;
}

// ---------------- 1: ligand center ----------------
__global__ void k_center(const float* __restrict__ lig) {
    int t = threadIdx.x;  // 32 threads
    float x = lig[t * 3 + 0], y = lig[t * 3 + 1], z = lig[t * 3 + 2];
    #pragma unroll
    for (int o = 16; o > 0; o >>= 1) {
        x += __shfl_down_sync(0xFFFFFFFFu, x, o);
        y += __shfl_down_sync(0xFFFFFFFFu, y, o);
        z += __shfl_down_sync(0xFFFFFFFFu, z, o);
    }
    if (t == 0) {
        g_center[0] = x * (1.0f / NLIG);
        g_center[1] = y * (1.0f / NLIG);
        g_center[2] = z * (1.0f / NLIG);
    }
}

// ---------------- 2: per-atom sq norm + ligand-distance score term ----------------
__global__ void k_base(const float* __restrict__ pos) {
    int i = blockIdx.x * blockDim.x + threadIdx.x;
    if (i >= NATOMS) return;
    float x = pos[i * 3 + 0], y = pos[i * 3 + 1], z = pos[i * 3 + 2];
    g_sq[i] = fmaf(z, z, fmaf(y, y, x * x));
    float dx = x - g_center[0], dy = y - g_center[1], dz = z - g_center[2];
    float d = sqrtf(fmaf(dz, dz, fmaf(dy, dy, dx * dx)));
    g_s0[i] = 1.0f / (1.0f + d / 5.0f);
}

// ---------------- 3: brute-force neighbor counting (d2 = sqi+sqj-2*dot < 9) ----------------
__global__ __launch_bounds__(256) void k_neighbor(const float* __restrict__ pos) {
    __shared__ float4 tile[256];
    int tid = threadIdx.x;
    int i = blockIdx.x * 256 + tid;
    float px = pos[i * 3 + 0], py = pos[i * 3 + 1], pz = pos[i * 3 + 2];
    float si = g_sq[i];
    int cnt = 0;
    int j0 = blockIdx.y * 2048;
    for (int jt = 0; jt < 8; jt++) {
        int j = j0 + jt * 256 + tid;
        tile[tid] = make_float4(pos[j * 3 + 0], pos[j * 3 + 1], pos[j * 3 + 2], g_sq[j]);
        __syncthreads();
        #pragma unroll 8
        for (int jj = 0; jj < 256; jj++) {
            float4 T = tile[jj];
            float dot = fmaf(pz, T.z, fmaf(py, T.y, px * T.x));
            float d2  = fmaf(-2.0f, dot, si + T.w);
            cnt += (d2 < 9.0f);
        }
        __syncthreads();
    }
    atomicAdd(&g_cnt[i], cnt);  // integer: deterministic
}

// ---------------- 4: final scores -> sortable keys + histogram ----------------
__global__ void k_scorekey() {
    int i = blockIdx.x * blockDim.x + threadIdx.x;
    if (i >= NATOMS) return;
    // count includes self; neighbor_counts = cnt-1; surface = 1/(nc+1) = 1/cnt
    float surface = 1.0f / (float)g_cnt[i];
    float s = g_s0[i] + 0.5f * surface;          // strictly positive
    unsigned key = __float_as_uint(s);           // monotone for positive floats
    g_keys[i] = key;
    atomicAdd(&g_hist[key >> 16], 1u);
}

// ---------------- 5: find threshold bin H and count r needed from it ----------------
__global__ void k_scan() {
    __shared__ unsigned csum[256];
    int t = threadIdx.x;
    unsigned s = 0;
    for (int b = t * 256; b < (t + 1) * 256; b++) s += g_hist[b];
    csum[t] = s;
    __syncthreads();
    if (t == 0) {
        unsigned g = 0;
        int chunk = 255;
        for (; chunk > 0; chunk--) {
            if (g + csum[chunk] >= (unsigned)NSEL) break;
            g += csum[chunk];
        }
        int H = chunk * 256;
        unsigned r = 1;
        for (int b = chunk * 256 + 255; b >= chunk * 256; b--) {
            unsigned c = g_hist[b];
            if (g + c >= (unsigned)NSEL) { H = b; r = (unsigned)NSEL - g; break; }
            g += c;
        }
        g_H = H;
        g_r = (int)r;
    }
}

// ---------------- 6: collect boundary-bin elements ----------------
__global__ void k_boundary() {
    int i = blockIdx.x * blockDim.x + threadIdx.x;
    if (i >= NATOMS) return;
    unsigned key = g_keys[i];
    if ((int)(key >> 16) == g_H) {
        int p = atomicAdd(&g_m, 1);
        // priority: higher score first, then lower index first
        g_bbuf[p] = ((ull)key << 32) | (ull)(0xFFFFFFFFu - (unsigned)i);
    }
}

// ---------------- 7: selection flags (exact top-k semantics incl. ties) ----------------
__global__ void k_flags() {
    int i = blockIdx.x * blockDim.x + threadIdx.x;
    if (i >= NATOMS) return;
    unsigned key = g_keys[i];
    int hi = (int)(key >> 16);
    int s = 0;
    if (hi > g_H) s = 1;
    else if (hi == g_H) {
        ull mine = ((ull)key << 32) | (ull)(0xFFFFFFFFu - (unsigned)i);
        int m = g_m, cnt = 0, r = g_r;
        for (int t = 0; t < m; t++) cnt += (g_bbuf[t] > mine);
        if (cnt < r) s = 1;
    }
    g_sel[i] = s;
}

// ---------------- 8: deterministic compaction (3 passes) ----------------
__global__ void k_bcount() {
    __shared__ int sm[256];
    int t = threadIdx.x;
    sm[t] = g_sel[blockIdx.x * 256 + t];
    __syncthreads();
    for (int o = 128; o > 0; o >>= 1) {
        if (t < o) sm[t] += sm[t + o];
        __syncthreads();
    }
    if (t == 0) g_bsum[blockIdx.x] = sm[0];
}
__global__ void k_boffsets() {
    if (threadIdx.x == 0) {
        int acc = 0;
        for (int b = 0; b < 64; b++) { g_boff[b] = acc; acc += g_bsum[b]; }
    }
}
__global__ void k_compact() {
    __shared__ int sc[256];
    int t = threadIdx.x;
    int i = blockIdx.x * 256 + t;
    int f = g_sel[i];
    sc[t] = f;
    __syncthreads();
    for (int o = 1; o < 256; o <<= 1) {
        int v = (t >= o) ? sc[t - o] : 0;
        __syncthreads();
        sc[t] += v;
        __syncthreads();
    }
    if (f) g_idx[g_boff[blockIdx.x] + sc[t] - 1] = i;
}

// ---------------- 9: fused gather + node-embed + QKV projection ----------------
__global__ __launch_bounds__(128) void k_qkv(
    const float* __restrict__ x,
    const float* __restrict__ Wn, const float* __restrict__ bn,
    const float* __restrict__ Wq, const float* __restrict__ bq,
    const float* __restrict__ Wk, const float* __restrict__ bk,
    const float* __restrict__ Wv, const float* __restrict__ bv)
{
    __shared__ float hs[4][HID];
    int c = threadIdx.x;
    int r0 = blockIdx.x * 4;
    #pragma unroll
    for (int rr = 0; rr < 4; rr++) {
        int row = g_idx[r0 + rr];
        const float* xr = x + row * NODE_F;
        float acc = bn[c];
        #pragma unroll
        for (int f = 0; f < NODE_F; f++) acc = fmaf(__ldg(xr + f), Wn[f * HID + c], acc);
        hs[rr][c] = acc;
    }
    __syncthreads();
    float aq[4], ak[4], av[4];
    #pragma unroll
    for (int rr = 0; rr < 4; rr++) { aq[rr] = bq[c]; ak[rr] = bk[c]; av[rr] = bv[c]; }
    for (int d = 0; d < HID; d++) {
        float wq = Wq[d * HID + c], wk = Wk[d * HID + c], wv = Wv[d * HID + c];
        #pragma unroll
        for (int rr = 0; rr < 4; rr++) {
            float h = hs[rr][d];
            aq[rr] = fmaf(h, wq, aq[rr]);
            ak[rr] = fmaf(h, wk, ak[rr]);
            av[rr] = fmaf(h, wv, av[rr]);
        }
    }
    #pragma unroll
    for (int rr = 0; rr < 4; rr++) {
        g_q[(r0 + rr) * HID + c] = aq[rr];
        g_k[(r0 + rr) * HID + c] = ak[rr];
        g_v[(r0 + rr) * HID + c] = av[rr];
    }
}

// ---------------- 10: flash-style attention, fp32, no max-subtraction ----------------
// logits ~ N(0,1): exp() cannot overflow fp32; softmax = sum(exp*v)/sum(exp).
__global__ __launch_bounds__(128) void k_attn() {
    __shared__ float4 Ks[128][4];
    __shared__ float4 Vs[128][4];
    int h = blockIdx.y;
    int tid = threadIdx.x;
    int qi = blockIdx.x * 128 + tid;

    const float scale = 0.25f;  // 1/sqrt(16)
    float qv[DH];
    #pragma unroll
    for (int d = 0; d < DH; d++) qv[d] = g_q[qi * HID + h * DH + d] * scale;

    float o[DH];
    #pragma unroll
    for (int d = 0; d < DH; d++) o[d] = 0.0f;
    float l = 0.0f;

    for (int kt = 0; kt < NSEL / 128; kt++) {
        int kr = kt * 128 + tid;
        const float4* kp = (const float4*)&g_k[kr * HID + h * DH];
        const float4* vp = (const float4*)&g_v[kr * HID + h * DH];
        Ks[tid][0] = kp[0]; Ks[tid][1] = kp[1]; Ks[tid][2] = kp[2]; Ks[tid][3] = kp[3];
        Vs[tid][0] = vp[0]; Vs[tid][1] = vp[1]; Vs[tid][2] = vp[2]; Vs[tid][3] = vp[3];
        __syncthreads();
        #pragma unroll 4
        for (int j = 0; j < 128; j++) {
            float4 a = Ks[j][0], b = Ks[j][1], c = Ks[j][2], d4 = Ks[j][3];
            float s;
            s = qv[0] * a.x;
            s = fmaf(qv[1],  a.y, s); s = fmaf(qv[2],  a.z, s); s = fmaf(qv[3],  a.w, s);
            s = fmaf(qv[4],  b.x, s); s = fmaf(qv[5],  b.y, s); s = fmaf(qv[6],  b.z, s);
            s = fmaf(qv[7],  b.w, s); s = fmaf(qv[8],  c.x, s); s = fmaf(qv[9],  c.y, s);
            s = fmaf(qv[10], c.z, s); s = fmaf(qv[11], c.w, s); s = fmaf(qv[12], d4.x, s);
            s = fmaf(qv[13], d4.y, s); s = fmaf(qv[14], d4.z, s); s = fmaf(qv[15], d4.w, s);
            float p = __expf(s);
            l += p;
            float4 va = Vs[j][0], vb = Vs[j][1], vc = Vs[j][2], vd = Vs[j][3];
            o[0]  = fmaf(p, va.x, o[0]);  o[1]  = fmaf(p, va.y, o[1]);
            o[2]  = fmaf(p, va.z, o[2]);  o[3]  = fmaf(p, va.w, o[3]);
            o[4]  = fmaf(p, vb.x, o[4]);  o[5]  = fmaf(p, vb.y, o[5]);
            o[6]  = fmaf(p, vb.z, o[6]);  o[7]  = fmaf(p, vb.w, o[7]);
            o[8]  = fmaf(p, vc.x, o[8]);  o[9]  = fmaf(p, vc.y, o[9]);
            o[10] = fmaf(p, vc.z, o[10]); o[11] = fmaf(p, vc.w, o[11]);
            o[12] = fmaf(p, vd.x, o[12]); o[13] = fmaf(p, vd.y, o[13]);
            o[14] = fmaf(p, vd.z, o[14]); o[15] = fmaf(p, vd.w, o[15]);
        }
        __syncthreads();
    }
    float inv = 1.0f / l;
    #pragma unroll
    for (int d = 0; d < DH; d++) g_av[qi * HID + h * DH + d] = o[d] * inv;
}

// ---------------- 11: deterministic column mean of av ----------------
__global__ void k_colsum() {
    __shared__ float sm[256];
    int col = blockIdx.x;
    int t = threadIdx.x;
    float s = 0.0f;
    for (int r = t; r < NSEL; r += 256) s += g_av[r * HID + col];
    sm[t] = s;
    __syncthreads();
    for (int o = 128; o > 0; o >>= 1) {
        if (t < o) sm[t] += sm[t + o];
        __syncthreads();
    }
    if (t == 0) g_mav[col] = sm[0] * (1.0f / NSEL);
}

// ---------------- 12: Wo + mean-pool commuted + MLP head ----------------
__global__ void k_final(
    const float* __restrict__ Wo, const float* __restrict__ bo,
    const float* __restrict__ W1, const float* __restrict__ b1,
    const float* __restrict__ W2, const float* __restrict__ b2,
    float* __restrict__ out)
{
    __shared__ float mav[HID];
    __shared__ float pooled[HID];
    __shared__ float t1[OUTD];
    int t = threadIdx.x;  // 256 threads
    if (t < HID) mav[t] = g_mav[t];
    __syncthreads();
    if (t < HID) {
        float acc = bo[t];
        for (int d = 0; d < HID; d++) acc = fmaf(mav[d], Wo[d * HID + t], acc);
        pooled[t] = acc;
    }
    __syncthreads();
    {
        float acc = b1[t];
        for (int d = 0; d < HID; d++) acc = fmaf(pooled[d], W1[d * OUTD + t], acc);
        t1[t] = fmaxf(acc, 0.0f);
    }
    __syncthreads();
    {
        float acc = b2[t];
        for (int d = 0; d < OUTD; d++) acc = fmaf(t1[d], W2[d * OUTD + t], acc);
        out[t] = acc;
    }
}

// ---------------- launcher ----------------
extern "C" void kernel_launch(void* const* d_in, const int* in_sizes, int n_in,
                              void* d_out, int out_size)
{
    const float* x    = (const float*)d_in[0];
    const float* pos  = (const float*)d_in[1];
    const float* lig  = (const float*)d_in[2];
    const float* Wn   = (const float*)d_in[3];
    const float* bn   = (const float*)d_in[4];
    const float* Wq   = (const float*)d_in[5];
    const float* bq   = (const float*)d_in[6];
    const float* Wk   = (const float*)d_in[7];
    const float* bk   = (const float*)d_in[8];
    const float* Wv   = (const float*)d_in[9];
    const float* bv   = (const float*)d_in[10];
    const float* Wo   = (const float*)d_in[11];
    const float* bo   = (const float*)d_in[12];
    const float* W1   = (const float*)d_in[13];
    const float* b1   = (const float*)d_in[14];
    const float* W2   = (const float*)d_in[15];
    const float* b2   = (const float*)d_in[16];
    float* out = (float*)d_out;

    k_zero<<<(NBINS + NATOMS + 255) / 256, 256>>>();
    k_center<<<1, 32>>>(lig);
    k_base<<<NATOMS / 256, 256>>>(pos);
    k_neighbor<<<dim3(NATOMS / 256, 8), 256>>>(pos);
    k_scorekey<<<NATOMS / 256, 256>>>();
    k_scan<<<1, 256>>>();
    k_boundary<<<NATOMS / 256, 256>>>();
    k_flags<<<NATOMS / 256, 256>>>();
    k_bcount<<<64, 256>>>();
    k_boffsets<<<1, 32>>>();
    k_compact<<<64, 256>>>();
    k_qkv<<<NSEL / 4, 128>>>(x, Wn, bn, Wq, bq, Wk, bk, Wv, bv);
    k_attn<<<dim3(NSEL / 128, HEADS), 128>>>();
    k_colsum<<<HID, 256>>>();
    k_final<<<1, 256>>>(Wo, bo, W1, b1, W2, b2, out);
}

// round 5
// speedup vs baseline: 1.0995x; 1.0994x over previous
#include <cuda_runtime.h>
#include <cuda_bf16.h>
#include <stdint.h>

// ---------------- problem constants ----------------
#define NATOMS   16384
#define NSEL     4096
#define NODE_F   8
#define HID      128
#define HEADS    8
#define DH       16
#define OUTD     256
#define NLIG     32
#define NBINS    65536

typedef unsigned long long ull;

// ---------------- packed f32x2 helpers (Blackwell FFMA2 path) ----------------
__device__ __forceinline__ ull f2_pack(float lo, float hi) {
    ull r; asm("mov.b64 %0, {%1, %2};" : "=l"(r) : "f"(lo), "f"(hi)); return r;
}
__device__ __forceinline__ void f2_unpack(ull v, float& lo, float& hi) {
    asm("mov.b64 {%0, %1}, %2;" : "=f"(lo), "=f"(hi) : "l"(v));
}
__device__ __forceinline__ ull f2_mul(ull a, ull b) {
    ull r; asm("mul.rn.f32x2 %0, %1, %2;" : "=l"(r) : "l"(a), "l"(b)); return r;
}
__device__ __forceinline__ ull f2_add(ull a, ull b) {
    ull r; asm("add.rn.f32x2 %0, %1, %2;" : "=l"(r) : "l"(a), "l"(b)); return r;
}
__device__ __forceinline__ ull f2_fma(ull a, ull b, ull c) {
    ull r; asm("fma.rn.f32x2 %0, %1, %2, %3;" : "=l"(r) : "l"(a), "l"(b), "l"(c)); return r;
}
__device__ __forceinline__ float ex2(float x) {
    float r; asm("ex2.approx.f32 %0, %1;" : "=f"(r) : "f"(x)); return r;
}

// ---------------- scratch (static device memory; no allocation) ----------------
__device__ float    g_center[3];
__device__ float    g_sq[NATOMS];
__device__ float    g_s0[NATOMS];
__device__ int      g_cnt[NATOMS];
__device__ unsigned g_keys[NATOMS];
__device__ unsigned g_hist[NBINS];
__device__ int      g_H;
__device__ int      g_r;
__device__ int      g_m;
__device__ ull      g_bbuf[NATOMS];
__device__ int      g_sel[NATOMS];
__device__ int      g_bsum[64];
__device__ int      g_boff[64];
__device__ int      g_idx[NSEL];
__device__ __align__(16) float g_q[NSEL * HID];
__device__ __align__(16) float g_k[NSEL * HID];
__device__ __align__(16) float g_v[NSEL * HID];
__device__ __align__(16) float g_po[2][NSEL * HID];   // split-K unnormalized outputs
__device__ float    g_pl[2][HEADS * NSEL];            // split-K softmax denominators
__device__ float    g_mav[HID];

// ---------------- 0: zero scratch that is accumulated into ----------------
__global__ void k_zero() {
    int i = blockIdx.x * blockDim.x + threadIdx.x;
    if (i < NBINS) g_hist[i] = 0;
    else if (i < NBINS + NATOMS) g_cnt[i - NBINS] = 0;
    if (i == 0) g_m = 0;
}

// ---------------- 1: ligand center + per-atom base terms (merged) ----------------
__global__ void k_center_base(const float* __restrict__ lig, const float* __restrict__ pos) {
    __shared__ float c3[3];
    int t = threadIdx.x;  // 1024 threads
    if (t < 32) {
        float x = lig[t * 3 + 0], y = lig[t * 3 + 1], z = lig[t * 3 + 2];
        #pragma unroll
        for (int o = 16; o > 0; o >>= 1) {
            x += __shfl_down_sync(0xFFFFFFFFu, x, o);
            y += __shfl_down_sync(0xFFFFFFFFu, y, o);
            z += __shfl_down_sync(0xFFFFFFFFu, z, o);
        }
        if (t == 0) {
            c3[0] = x * (1.0f / NLIG);
            c3[1] = y * (1.0f / NLIG);
            c3[2] = z * (1.0f / NLIG);
            g_center[0] = c3[0]; g_center[1] = c3[1]; g_center[2] = c3[2];
        }
    }
    __syncthreads();
    float cx = c3[0], cy = c3[1], cz = c3[2];
    for (int i = t; i < NATOMS; i += 1024) {
        float x = pos[i * 3 + 0], y = pos[i * 3 + 1], z = pos[i * 3 + 2];
        g_sq[i] = fmaf(z, z, fmaf(y, y, x * x));
        float dx = x - cx, dy = y - cy, dz = z - cz;
        float d = sqrtf(fmaf(dz, dz, fmaf(dy, dy, dx * dx)));
        g_s0[i] = 1.0f / (1.0f + d / 5.0f);
    }
}

// ---------------- 2: neighbor counting, FFMA2-packed (2 j-atoms per iter) ----------------
// d2 < 9  <=>  dot - 0.5*sw - 0.5*si + 4.5 > 0
__global__ __launch_bounds__(256) void k_neighbor(const float* __restrict__ pos) {
    __shared__ ull sX[128], sY[128], sZ[128], sW[128];
    int tid = threadIdx.x;
    int i = blockIdx.x * 256 + tid;
    float px = pos[i * 3 + 0], py = pos[i * 3 + 1], pz = pos[i * 3 + 2];
    float ci = 4.5f - 0.5f * g_sq[i];
    ull px2 = f2_pack(px, px), py2 = f2_pack(py, py), pz2 = f2_pack(pz, pz);
    ull ci2 = f2_pack(ci, ci);
    float* fX = (float*)sX; float* fY = (float*)sY; float* fZ = (float*)sZ; float* fW = (float*)sW;
    int cnt = 0;
    int j0 = blockIdx.y * 2048;
    for (int jt = 0; jt < 8; jt++) {
        int j = j0 + jt * 256 + tid;
        fX[tid] = pos[j * 3 + 0];
        fY[tid] = pos[j * 3 + 1];
        fZ[tid] = pos[j * 3 + 2];
        fW[tid] = -0.5f * g_sq[j];
        __syncthreads();
        #pragma unroll 4
        for (int jp = 0; jp < 128; jp++) {
            ull base = f2_add(sW[jp], ci2);
            ull v = f2_fma(px2, sX[jp], f2_fma(py2, sY[jp], f2_fma(pz2, sZ[jp], base)));
            float vlo, vhi; f2_unpack(v, vlo, vhi);
            cnt += (vlo > 0.0f);
            cnt += (vhi > 0.0f);
        }
        __syncthreads();
    }
    atomicAdd(&g_cnt[i], cnt);  // integer: deterministic
}

// ---------------- 3: final scores -> sortable keys + histogram ----------------
__global__ void k_scorekey() {
    int i = blockIdx.x * blockDim.x + threadIdx.x;
    if (i >= NATOMS) return;
    float surface = 1.0f / (float)g_cnt[i];       // cnt includes self
    float s = g_s0[i] + 0.5f * surface;           // strictly positive
    unsigned key = __float_as_uint(s);
    g_keys[i] = key;
    atomicAdd(&g_hist[key >> 16], 1u);
}

// ---------------- 4: find threshold bin H and count r needed from it ----------------
__global__ void k_scan() {
    __shared__ unsigned csum[256];
    int t = threadIdx.x;
    unsigned s = 0;
    for (int b = t * 256; b < (t + 1) * 256; b++) s += g_hist[b];
    csum[t] = s;
    __syncthreads();
    if (t == 0) {
        unsigned g = 0;
        int chunk = 255;
        for (; chunk > 0; chunk--) {
            if (g + csum[chunk] >= (unsigned)NSEL) break;
            g += csum[chunk];
        }
        int H = chunk * 256;
        unsigned r = 1;
        for (int b = chunk * 256 + 255; b >= chunk * 256; b--) {
            unsigned c = g_hist[b];
            if (g + c >= (unsigned)NSEL) { H = b; r = (unsigned)NSEL - g; break; }
            g += c;
        }
        g_H = H;
        g_r = (int)r;
    }
}

// ---------------- 5: collect boundary-bin elements ----------------
__global__ void k_boundary() {
    int i = blockIdx.x * blockDim.x + threadIdx.x;
    if (i >= NATOMS) return;
    unsigned key = g_keys[i];
    if ((int)(key >> 16) == g_H) {
        int p = atomicAdd(&g_m, 1);
        g_bbuf[p] = ((ull)key << 32) | (ull)(0xFFFFFFFFu - (unsigned)i);
    }
}

// ---------------- 6: selection flags (exact top-k semantics incl. ties) ----------------
__global__ void k_flags() {
    int i = blockIdx.x * blockDim.x + threadIdx.x;
    if (i >= NATOMS) return;
    unsigned key = g_keys[i];
    int hi = (int)(key >> 16);
    int s = 0;
    if (hi > g_H) s = 1;
    else if (hi == g_H) {
        ull mine = ((ull)key << 32) | (ull)(0xFFFFFFFFu - (unsigned)i);
        int m = g_m, cnt = 0, r = g_r;
        for (int t = 0; t < m; t++) cnt += (g_bbuf[t] > mine);
        if (cnt < r) s = 1;
    }
    g_sel[i] = s;
}

// ---------------- 7: deterministic compaction (3 passes) ----------------
__global__ void k_bcount() {
    __shared__ int sm[256];
    int t = threadIdx.x;
    sm[t] = g_sel[blockIdx.x * 256 + t];
    __syncthreads();
    for (int o = 128; o > 0; o >>= 1) {
        if (t < o) sm[t] += sm[t + o];
        __syncthreads();
    }
    if (t == 0) g_bsum[blockIdx.x] = sm[0];
}
__global__ void k_boffsets() {
    if (threadIdx.x == 0) {
        int acc = 0;
        for (int b = 0; b < 64; b++) { g_boff[b] = acc; acc += g_bsum[b]; }
    }
}
__global__ void k_compact() {
    __shared__ int sc[256];
    int t = threadIdx.x;
    int i = blockIdx.x * 256 + t;
    int f = g_sel[i];
    sc[t] = f;
    __syncthreads();
    for (int o = 1; o < 256; o <<= 1) {
        int v = (t >= o) ? sc[t - o] : 0;
        __syncthreads();
        sc[t] += v;
        __syncthreads();
    }
    if (f) g_idx[g_boff[blockIdx.x] + sc[t] - 1] = i;
}

// ---------------- 8: fused gather + node-embed + QKV projection ----------------
__global__ __launch_bounds__(128) void k_qkv(
    const float* __restrict__ x,
    const float* __restrict__ Wn, const float* __restrict__ bn,
    const float* __restrict__ Wq, const float* __restrict__ bq,
    const float* __restrict__ Wk, const float* __restrict__ bk,
    const float* __restrict__ Wv, const float* __restrict__ bv)
{
    __shared__ float hs[4][HID];
    int c = threadIdx.x;
    int r0 = blockIdx.x * 4;
    #pragma unroll
    for (int rr = 0; rr < 4; rr++) {
        int row = g_idx[r0 + rr];
        const float* xr = x + row * NODE_F;
        float acc = bn[c];
        #pragma unroll
        for (int f = 0; f < NODE_F; f++) acc = fmaf(__ldg(xr + f), Wn[f * HID + c], acc);
        hs[rr][c] = acc;
    }
    __syncthreads();
    float aq[4], ak[4], av[4];
    #pragma unroll
    for (int rr = 0; rr < 4; rr++) { aq[rr] = bq[c]; ak[rr] = bk[c]; av[rr] = bv[c]; }
    for (int d = 0; d < HID; d++) {
        float wq = Wq[d * HID + c], wk = Wk[d * HID + c], wv = Wv[d * HID + c];
        #pragma unroll
        for (int rr = 0; rr < 4; rr++) {
            float h = hs[rr][d];
            aq[rr] = fmaf(h, wq, aq[rr]);
            ak[rr] = fmaf(h, wk, ak[rr]);
            av[rr] = fmaf(h, wv, av[rr]);
        }
    }
    #pragma unroll
    for (int rr = 0; rr < 4; rr++) {
        g_q[(r0 + rr) * HID + c] = aq[rr];
        g_k[(r0 + rr) * HID + c] = ak[rr];
        g_v[(r0 + rr) * HID + c] = av[rr];
    }
}

// ---------------- 9: attention, f32x2-packed, split-K x2 ----------------
// logits ~ N(0,1): exp cannot overflow fp32 -> no max subtraction needed.
// Q pre-scaled by 0.25*log2(e); p = ex2(q'.k)  (same MUFU.EX2 path as __expf).
// Packing: QK packs 2 keys/lane (K tile transposed in smem); PV packs 2 d/lane.
__global__ __launch_bounds__(128) void k_attn() {
    __shared__ ull Kp[16 * 64];    // Kp[d*64 + jp] = (K[2jp][d], K[2jp+1][d])
    __shared__ ull Vsm[128 * 8];   // row-major: 8 packed d-pairs per key
    int h = blockIdx.y;
    int split = blockIdx.z;
    int tid = threadIdx.x;
    int qi = blockIdx.x * 128 + tid;

    const float cs = 0.25f * 1.4426950408889634f;  // scale * log2(e)
    ull qd[16];
    #pragma unroll
    for (int d = 0; d < DH; d++) {
        float qv = g_q[qi * HID + h * DH + d] * cs;
        qd[d] = f2_pack(qv, qv);
    }
    ull o2[8];
    #pragma unroll
    for (int dp = 0; dp < 8; dp++) o2[dp] = 0ull;   // bit pattern of (0.f, 0.f)
    float l0 = 0.0f, l1 = 0.0f;

    float* KpF = (float*)Kp;
    for (int kt = split * 16; kt < split * 16 + 16; kt++) {
        int kr = kt * 128 + tid;
        // transpose K tile into smem: KpF[d*128 + tid] (bank-conflict-free)
        const float4* k4 = (const float4*)(g_k + kr * HID + h * DH);
        float4 a = k4[0], b = k4[1], c4 = k4[2], d4 = k4[3];
        KpF[ 0*128+tid]=a.x;  KpF[ 1*128+tid]=a.y;  KpF[ 2*128+tid]=a.z;  KpF[ 3*128+tid]=a.w;
        KpF[ 4*128+tid]=b.x;  KpF[ 5*128+tid]=b.y;  KpF[ 6*128+tid]=b.z;  KpF[ 7*128+tid]=b.w;
        KpF[ 8*128+tid]=c4.x; KpF[ 9*128+tid]=c4.y; KpF[10*128+tid]=c4.z; KpF[11*128+tid]=c4.w;
        KpF[12*128+tid]=d4.x; KpF[13*128+tid]=d4.y; KpF[14*128+tid]=d4.z; KpF[15*128+tid]=d4.w;
        // V tile row-major (natural d-pair packing)
        const ulonglong2* gv = (const ulonglong2*)(g_v + kr * HID + h * DH);
        ulonglong2* vd = (ulonglong2*)(Vsm + tid * 8);
        vd[0] = gv[0]; vd[1] = gv[1]; vd[2] = gv[2]; vd[3] = gv[3];
        __syncthreads();

        for (int jp = 0; jp < 64; jp++) {
            const ull* kc = Kp + jp;
            ull sa = f2_mul(qd[0], kc[0]);
            ull sb = f2_mul(qd[8], kc[8 * 64]);
            #pragma unroll
            for (int d = 1; d < 8; d++) {
                sa = f2_fma(qd[d],     kc[d * 64],       sa);
                sb = f2_fma(qd[d + 8], kc[(d + 8) * 64], sb);
            }
            ull s2 = f2_add(sa, sb);
            float slo, shi; f2_unpack(s2, slo, shi);
            float p0 = ex2(slo), p1 = ex2(shi);
            l0 += p0; l1 += p1;
            ull p0d = f2_pack(p0, p0), p1d = f2_pack(p1, p1);
            const ulonglong2* v0 = (const ulonglong2*)(Vsm + (2 * jp) * 8);
            const ulonglong2* v1 = (const ulonglong2*)(Vsm + (2 * jp + 1) * 8);
            #pragma unroll
            for (int q2 = 0; q2 < 4; q2++) {
                ulonglong2 va = v0[q2], vb = v1[q2];
                o2[q2 * 2]     = f2_fma(p0d, va.x, o2[q2 * 2]);
                o2[q2 * 2 + 1] = f2_fma(p0d, va.y, o2[q2 * 2 + 1]);
                o2[q2 * 2]     = f2_fma(p1d, vb.x, o2[q2 * 2]);
                o2[q2 * 2 + 1] = f2_fma(p1d, vb.y, o2[q2 * 2 + 1]);
            }
        }
        __syncthreads();
    }
    ull* po = (ull*)(g_po[split] + qi * HID + h * DH);
    #pragma unroll
    for (int dp = 0; dp < 8; dp++) po[dp] = o2[dp];
    g_pl[split][h * NSEL + qi] = l0 + l1;
}

// ---------------- 10: combine split-K partials + deterministic column mean ----------------
__global__ void k_colsum() {
    __shared__ float sm[256];
    int col = blockIdx.x;
    int h = col >> 4;
    int t = threadIdx.x;
    float s = 0.0f;
    for (int r = t; r < NSEL; r += 256) {
        float l   = g_pl[0][h * NSEL + r] + g_pl[1][h * NSEL + r];
        float num = g_po[0][r * HID + col] + g_po[1][r * HID + col];
        s += num / l;
    }
    sm[t] = s;
    __syncthreads();
    for (int o = 128; o > 0; o >>= 1) {
        if (t < o) sm[t] += sm[t + o];
        __syncthreads();
    }
    if (t == 0) g_mav[col] = sm[0] * (1.0f / NSEL);
}

// ---------------- 11: Wo + mean-pool commuted + MLP head ----------------
__global__ void k_final(
    const float* __restrict__ Wo, const float* __restrict__ bo,
    const float* __restrict__ W1, const float* __restrict__ b1,
    const float* __restrict__ W2, const float* __restrict__ b2,
    float* __restrict__ out)
{
    __shared__ float mav[HID];
    __shared__ float pooled[HID];
    __shared__ float t1[OUTD];
    int t = threadIdx.x;  // 256 threads
    if (t < HID) mav[t] = g_mav[t];
    __syncthreads();
    if (t < HID) {
        float acc = bo[t];
        for (int d = 0; d < HID; d++) acc = fmaf(mav[d], Wo[d * HID + t], acc);
        pooled[t] = acc;
    }
    __syncthreads();
    {
        float acc = b1[t];
        for (int d = 0; d < HID; d++) acc = fmaf(pooled[d], W1[d * OUTD + t], acc);
        t1[t] = fmaxf(acc, 0.0f);
    }
    __syncthreads();
    {
        float acc = b2[t];
        for (int d = 0; d < OUTD; d++) acc = fmaf(t1[d], W2[d * OUTD + t], acc);
        out[t] = acc;
    }
}

// ---------------- launcher ----------------
extern "C" void kernel_launch(void* const* d_in, const int* in_sizes, int n_in,
                              void* d_out, int out_size)
{
    const float* x    = (const float*)d_in[0];
    const float* pos  = (const float*)d_in[1];
    const float* lig  = (const float*)d_in[2];
    const float* Wn   = (const float*)d_in[3];
    const float* bn   = (const float*)d_in[4];
    const float* Wq   = (const float*)d_in[5];
    const float* bq   = (const float*)d_in[6];
    const float* Wk   = (const float*)d_in[7];
    const float* bk   = (const float*)d_in[8];
    const float* Wv   = (const float*)d_in[9];
    const float* bv   = (const float*)d_in[10];
    const float* Wo   = (const float*)d_in[11];
    const float* bo   = (const float*)d_in[12];
    const float* W1   = (const float*)d_in[13];
    const float* b1   = (const float*)d_in[14];
    const float* W2   = (const float*)d_in[15];
    const float* b2   = (const float*)d_in[16];
    float* out = (float*)d_out;

    k_zero<<<(NBINS + NATOMS + 255) / 256, 256>>>();
    k_center_base<<<1, 1024>>>(lig, pos);
    k_neighbor<<<dim3(NATOMS / 256, 8), 256>>>(pos);
    k_scorekey<<<NATOMS / 256, 256>>>();
    k_scan<<<1, 256>>>();
    k_boundary<<<NATOMS / 256, 256>>>();
    k_flags<<<NATOMS / 256, 256>>>();
    k_bcount<<<64, 256>>>();
    k_boffsets<<<1, 32>>>();
    k_compact<<<64, 256>>>();
    k_qkv<<<NSEL / 4, 128>>>(x, Wn, bn, Wq, bq, Wk, bk, Wv, bv);
    k_attn<<<dim3(NSEL / 128, HEADS, 2), 128>>>();
    k_colsum<<<HID, 256>>>();
    k_final<<<1, 256>>>(Wo, bo, W1, b1, W2, b2, out);
}

// round 7
// speedup vs baseline: 1.7226x; 1.5667x over previous
#include <cuda_runtime.h>
#include <cuda_bf16.h>
#include <stdint.h>

// ---------------- problem constants ----------------
#define NATOMS   16384
#define NSEL     4096
#define NODE_F   8
#define HID      128
#define HEADS    8
#define DH       16
#define OUTD     256
#define NLIG     32
#define NBINS    65536

#define TQ 64      // queries per attention block (16 per warp)
#define TK 128     // keys per smem tile
#define KPAD 24    // smem row stride in bf16 (48B: 16B-aligned, ldmatrix conflict-free)

typedef unsigned long long ull;

// ---------------- packed f32x2 helpers (Blackwell FFMA2 path) ----------------
__device__ __forceinline__ ull f2_pack(float lo, float hi) {
    ull r; asm("mov.b64 %0, {%1, %2};" : "=l"(r) : "f"(lo), "f"(hi)); return r;
}
__device__ __forceinline__ void f2_unpack(ull v, float& lo, float& hi) {
    asm("mov.b64 {%0, %1}, %2;" : "=f"(lo), "=f"(hi) : "l"(v));
}
__device__ __forceinline__ ull f2_add(ull a, ull b) {
    ull r; asm("add.rn.f32x2 %0, %1, %2;" : "=l"(r) : "l"(a), "l"(b)); return r;
}
__device__ __forceinline__ ull f2_fma(ull a, ull b, ull c) {
    ull r; asm("fma.rn.f32x2 %0, %1, %2, %3;" : "=l"(r) : "l"(a), "l"(b), "l"(c)); return r;
}
__device__ __forceinline__ float ex2(float x) {
    float r; asm("ex2.approx.f32 %0, %1;" : "=f"(r) : "f"(x)); return r;
}

// ---------------- tensor-core helpers ----------------
__device__ __forceinline__ unsigned scvt(const void* p) {
    return (unsigned)__cvta_generic_to_shared(p);
}
__device__ __forceinline__ void ldm_x4(unsigned* r, unsigned a) {
    asm volatile("ldmatrix.sync.aligned.m8n8.x4.shared.b16 {%0,%1,%2,%3}, [%4];"
        : "=r"(r[0]), "=r"(r[1]), "=r"(r[2]), "=r"(r[3]) : "r"(a));
}
__device__ __forceinline__ void ldm_x2(unsigned* r, unsigned a) {
    asm volatile("ldmatrix.sync.aligned.m8n8.x2.shared.b16 {%0,%1}, [%2];"
        : "=r"(r[0]), "=r"(r[1]) : "r"(a));
}
__device__ __forceinline__ void ldm_x2t(unsigned* r, unsigned a) {
    asm volatile("ldmatrix.sync.aligned.m8n8.x2.trans.shared.b16 {%0,%1}, [%2];"
        : "=r"(r[0]), "=r"(r[1]) : "r"(a));
}
__device__ __forceinline__ void mma16816(float* d, const unsigned* a, const unsigned* b) {
    asm volatile(
        "mma.sync.aligned.m16n8k16.row.col.f32.bf16.bf16.f32 "
        "{%0,%1,%2,%3}, {%4,%5,%6,%7}, {%8,%9}, {%0,%1,%2,%3};"
        : "+f"(d[0]), "+f"(d[1]), "+f"(d[2]), "+f"(d[3])
        : "r"(a[0]), "r"(a[1]), "r"(a[2]), "r"(a[3]), "r"(b[0]), "r"(b[1]));
}
__device__ __forceinline__ unsigned cvt_bf16x2(float lo, float hi) {
    unsigned r;
    asm("cvt.rn.bf16x2.f32 %0, %1, %2;" : "=r"(r) : "f"(hi), "f"(lo));  // d.hi=%1, d.lo=%2
    return r;
}

// ---------------- scratch (static device memory; no allocation) ----------------
__device__ float    g_center[3];
__device__ float    g_sq[NATOMS];
__device__ float    g_s0[NATOMS];
__device__ int      g_cnt[NATOMS];
__device__ unsigned g_keys[NATOMS];
__device__ unsigned g_hist[NBINS];
__device__ int      g_H;
__device__ int      g_r;
__device__ int      g_m;
__device__ ull      g_bbuf[NATOMS];
__device__ int      g_sel[NATOMS];
__device__ int      g_bsum[64];
__device__ int      g_boff[64];
__device__ int      g_idx[NSEL];
__device__ __align__(16) __nv_bfloat16 g_qh[NSEL * HID];  // q * scale*log2e, hi part
__device__ __align__(16) __nv_bfloat16 g_ql[NSEL * HID];  // residual
__device__ __align__(16) __nv_bfloat16 g_kh[NSEL * HID];
__device__ __align__(16) __nv_bfloat16 g_kl[NSEL * HID];
__device__ __align__(16) __nv_bfloat16 g_vh[NSEL * HID];  // V hi part
__device__ __align__(16) __nv_bfloat16 g_vl[NSEL * HID];  // V residual
__device__ __align__(16) float g_av[NSEL * HID];
__device__ float    g_mav[HID];

// ---------------- 0: zero scratch that is accumulated into ----------------
__global__ void k_zero() {
    int i = blockIdx.x * blockDim.x + threadIdx.x;
    if (i < NBINS) g_hist[i] = 0;
    else if (i < NBINS + NATOMS) g_cnt[i - NBINS] = 0;
    if (i == 0) g_m = 0;
}

// ---------------- 1: ligand center + per-atom base terms (merged) ----------------
__global__ void k_center_base(const float* __restrict__ lig, const float* __restrict__ pos) {
    __shared__ float c3[3];
    int t = threadIdx.x;  // 1024 threads
    if (t < 32) {
        float x = lig[t * 3 + 0], y = lig[t * 3 + 1], z = lig[t * 3 + 2];
        #pragma unroll
        for (int o = 16; o > 0; o >>= 1) {
            x += __shfl_down_sync(0xFFFFFFFFu, x, o);
            y += __shfl_down_sync(0xFFFFFFFFu, y, o);
            z += __shfl_down_sync(0xFFFFFFFFu, z, o);
        }
        if (t == 0) {
            c3[0] = x * (1.0f / NLIG);
            c3[1] = y * (1.0f / NLIG);
            c3[2] = z * (1.0f / NLIG);
            g_center[0] = c3[0]; g_center[1] = c3[1]; g_center[2] = c3[2];
        }
    }
    __syncthreads();
    float cx = c3[0], cy = c3[1], cz = c3[2];
    for (int i = t; i < NATOMS; i += 1024) {
        float x = pos[i * 3 + 0], y = pos[i * 3 + 1], z = pos[i * 3 + 2];
        g_sq[i] = fmaf(z, z, fmaf(y, y, x * x));
        float dx = x - cx, dy = y - cy, dz = z - cz;
        float d = sqrtf(fmaf(dz, dz, fmaf(dy, dy, dx * dx)));
        g_s0[i] = 1.0f / (1.0f + d / 5.0f);
    }
}

// ---------------- 2: neighbor counting, FFMA2-packed (2 j-atoms per iter) ----------------
__global__ __launch_bounds__(256) void k_neighbor(const float* __restrict__ pos) {
    __shared__ ull sX[128], sY[128], sZ[128], sW[128];
    int tid = threadIdx.x;
    int i = blockIdx.x * 256 + tid;
    float px = pos[i * 3 + 0], py = pos[i * 3 + 1], pz = pos[i * 3 + 2];
    float ci = 4.5f - 0.5f * g_sq[i];
    ull px2 = f2_pack(px, px), py2 = f2_pack(py, py), pz2 = f2_pack(pz, pz);
    ull ci2 = f2_pack(ci, ci);
    float* fX = (float*)sX; float* fY = (float*)sY; float* fZ = (float*)sZ; float* fW = (float*)sW;
    int cnt = 0;
    int j0 = blockIdx.y * 2048;
    for (int jt = 0; jt < 8; jt++) {
        int j = j0 + jt * 256 + tid;
        fX[tid] = pos[j * 3 + 0];
        fY[tid] = pos[j * 3 + 1];
        fZ[tid] = pos[j * 3 + 2];
        fW[tid] = -0.5f * g_sq[j];
        __syncthreads();
        #pragma unroll 4
        for (int jp = 0; jp < 128; jp++) {
            ull base = f2_add(sW[jp], ci2);
            ull v = f2_fma(px2, sX[jp], f2_fma(py2, sY[jp], f2_fma(pz2, sZ[jp], base)));
            float vlo, vhi; f2_unpack(v, vlo, vhi);
            cnt += (vlo > 0.0f);
            cnt += (vhi > 0.0f);
        }
        __syncthreads();
    }
    atomicAdd(&g_cnt[i], cnt);
}

// ---------------- 3: final scores -> sortable keys + histogram ----------------
__global__ void k_scorekey() {
    int i = blockIdx.x * blockDim.x + threadIdx.x;
    if (i >= NATOMS) return;
    float surface = 1.0f / (float)g_cnt[i];
    float s = g_s0[i] + 0.5f * surface;
    unsigned key = __float_as_uint(s);
    g_keys[i] = key;
    atomicAdd(&g_hist[key >> 16], 1u);
}

// ---------------- 4: threshold bin ----------------
__global__ void k_scan() {
    __shared__ unsigned csum[256];
    int t = threadIdx.x;
    unsigned s = 0;
    for (int b = t * 256; b < (t + 1) * 256; b++) s += g_hist[b];
    csum[t] = s;
    __syncthreads();
    if (t == 0) {
        unsigned g = 0;
        int chunk = 255;
        for (; chunk > 0; chunk--) {
            if (g + csum[chunk] >= (unsigned)NSEL) break;
            g += csum[chunk];
        }
        int H = chunk * 256;
        unsigned r = 1;
        for (int b = chunk * 256 + 255; b >= chunk * 256; b--) {
            unsigned c = g_hist[b];
            if (g + c >= (unsigned)NSEL) { H = b; r = (unsigned)NSEL - g; break; }
            g += c;
        }
        g_H = H;
        g_r = (int)r;
    }
}

// ---------------- 5: boundary-bin elements ----------------
__global__ void k_boundary() {
    int i = blockIdx.x * blockDim.x + threadIdx.x;
    if (i >= NATOMS) return;
    unsigned key = g_keys[i];
    if ((int)(key >> 16) == g_H) {
        int p = atomicAdd(&g_m, 1);
        g_bbuf[p] = ((ull)key << 32) | (ull)(0xFFFFFFFFu - (unsigned)i);
    }
}

// ---------------- 6: selection flags ----------------
__global__ void k_flags() {
    int i = blockIdx.x * blockDim.x + threadIdx.x;
    if (i >= NATOMS) return;
    unsigned key = g_keys[i];
    int hi = (int)(key >> 16);
    int s = 0;
    if (hi > g_H) s = 1;
    else if (hi == g_H) {
        ull mine = ((ull)key << 32) | (ull)(0xFFFFFFFFu - (unsigned)i);
        int m = g_m, cnt = 0, r = g_r;
        for (int t = 0; t < m; t++) cnt += (g_bbuf[t] > mine);
        if (cnt < r) s = 1;
    }
    g_sel[i] = s;
}

// ---------------- 7: deterministic compaction ----------------
__global__ void k_bcount() {
    __shared__ int sm[256];
    int t = threadIdx.x;
    sm[t] = g_sel[blockIdx.x * 256 + t];
    __syncthreads();
    for (int o = 128; o > 0; o >>= 1) {
        if (t < o) sm[t] += sm[t + o];
        __syncthreads();
    }
    if (t == 0) g_bsum[blockIdx.x] = sm[0];
}
__global__ void k_boffsets() {
    if (threadIdx.x == 0) {
        int acc = 0;
        for (int b = 0; b < 64; b++) { g_boff[b] = acc; acc += g_bsum[b]; }
    }
}
__global__ void k_compact() {
    __shared__ int sc[256];
    int t = threadIdx.x;
    int i = blockIdx.x * 256 + t;
    int f = g_sel[i];
    sc[t] = f;
    __syncthreads();
    for (int o = 1; o < 256; o <<= 1) {
        int v = (t >= o) ? sc[t - o] : 0;
        __syncthreads();
        sc[t] += v;
        __syncthreads();
    }
    if (f) g_idx[g_boff[blockIdx.x] + sc[t] - 1] = i;
}

// ---------------- 8: gather + embed + QKV; emit bf16 hi/lo operands ----------------
__global__ __launch_bounds__(128) void k_qkv(
    const float* __restrict__ x,
    const float* __restrict__ Wn, const float* __restrict__ bn,
    const float* __restrict__ Wq, const float* __restrict__ bq,
    const float* __restrict__ Wk, const float* __restrict__ bk,
    const float* __restrict__ Wv, const float* __restrict__ bv)
{
    __shared__ float hs[4][HID];
    int c = threadIdx.x;
    int r0 = blockIdx.x * 4;
    #pragma unroll
    for (int rr = 0; rr < 4; rr++) {
        int row = g_idx[r0 + rr];
        const float* xr = x + row * NODE_F;
        float acc = bn[c];
        #pragma unroll
        for (int f = 0; f < NODE_F; f++) acc = fmaf(__ldg(xr + f), Wn[f * HID + c], acc);
        hs[rr][c] = acc;
    }
    __syncthreads();
    float aq[4], ak[4], av[4];
    #pragma unroll
    for (int rr = 0; rr < 4; rr++) { aq[rr] = bq[c]; ak[rr] = bk[c]; av[rr] = bv[c]; }
    for (int d = 0; d < HID; d++) {
        float wq = Wq[d * HID + c], wk = Wk[d * HID + c], wv = Wv[d * HID + c];
        #pragma unroll
        for (int rr = 0; rr < 4; rr++) {
            float h = hs[rr][d];
            aq[rr] = fmaf(h, wq, aq[rr]);
            ak[rr] = fmaf(h, wk, ak[rr]);
            av[rr] = fmaf(h, wv, av[rr]);
        }
    }
    const float cs = 0.25f * 1.4426950408889634f;  // scale * log2(e), folded into Q
    #pragma unroll
    for (int rr = 0; rr < 4; rr++) {
        int o = (r0 + rr) * HID + c;
        float qs = aq[rr] * cs;
        __nv_bfloat16 qhi = __float2bfloat16(qs);
        g_qh[o] = qhi;
        g_ql[o] = __float2bfloat16(qs - __bfloat162float(qhi));
        float kf = ak[rr];
        __nv_bfloat16 khi = __float2bfloat16(kf);
        g_kh[o] = khi;
        g_kl[o] = __float2bfloat16(kf - __bfloat162float(khi));
        float vf = av[rr];
        __nv_bfloat16 vhi = __float2bfloat16(vf);
        g_vh[o] = vhi;
        g_vl[o] = __float2bfloat16(vf - __bfloat162float(vhi));
    }
}

// ---------------- 9: tensor-core attention (bf16 split, fp32 accum) ----------------
// S = Qhi·Khi + Qhi·Klo + Qlo·Khi (~fp32 logits); p = ex2(S);
// O = P·Vhi + P·Vlo (V split kills the systematic bf16-V quantization that
// survives the query-mean pool). No max-subtraction: logits ~ N(0,1).
__global__ __launch_bounds__(128) void k_attn_tc() {
    __shared__ __align__(16) __nv_bfloat16 sKh[TK][KPAD];
    __shared__ __align__(16) __nv_bfloat16 sKl[TK][KPAD];
    __shared__ __align__(16) __nv_bfloat16 sVh[TK][KPAD];
    __shared__ __align__(16) __nv_bfloat16 sVl[TK][KPAD];

    int h    = blockIdx.y;
    int q0   = blockIdx.x * TQ;
    int tid  = threadIdx.x;
    int warp = tid >> 5;
    int lane = tid & 31;

    // ---- stage Q tile (64 rows x 16 cols, hi+lo) into K buffers, ldmatrix to regs ----
    {
        int row = tid >> 1, half = tid & 1;
        const uint4* sh = (const uint4*)(g_qh + (q0 + row) * HID + h * DH + half * 8);
        const uint4* sl = (const uint4*)(g_ql + (q0 + row) * HID + h * DH + half * 8);
        *(uint4*)&sKh[row][half * 8] = *sh;
        *(uint4*)&sKl[row][half * 8] = *sl;
    }
    __syncthreads();
    unsigned a_hi[4], a_lo[4];
    {
        int mrow = warp * 16 + ((lane >> 3) & 1) * 8 + (lane & 7);
        unsigned coff = (lane >> 4) * 16;
        ldm_x4(a_hi, scvt(&sKh[mrow][0]) + coff);
        ldm_x4(a_lo, scvt(&sKl[mrow][0]) + coff);
    }
    __syncthreads();

    float o[8];
    #pragma unroll
    for (int i = 0; i < 8; i++) o[i] = 0.0f;
    float l0 = 0.0f, l1 = 0.0f;

    // per-lane ldmatrix address components
    int brow8  = lane & 7;                            // QK B: 8 key rows, d halves
    unsigned bcoff = ((lane >> 3) & 1) * 16;
    int vrow16 = (lane & 7) + ((lane >> 3) & 1) * 8;  // PV B: 16 key rows

    for (int kt = 0; kt < NSEL / TK; kt++) {
        {
            int row = tid;  // 128 rows
            int src = (kt * TK + row) * HID + h * DH;
            const uint4* kh = (const uint4*)(g_kh + src);
            const uint4* kl = (const uint4*)(g_kl + src);
            const uint4* vh = (const uint4*)(g_vh + src);
            const uint4* vl = (const uint4*)(g_vl + src);
            *(uint4*)&sKh[row][0] = kh[0]; *(uint4*)&sKh[row][8] = kh[1];
            *(uint4*)&sKl[row][0] = kl[0]; *(uint4*)&sKl[row][8] = kl[1];
            *(uint4*)&sVh[row][0] = vh[0]; *(uint4*)&sVh[row][8] = vh[1];
            *(uint4*)&sVl[row][0] = vl[0]; *(uint4*)&sVl[row][8] = vl[1];
        }
        __syncthreads();

        #pragma unroll
        for (int g16 = 0; g16 < TK / 16; g16++) {
            float S[8];
            #pragma unroll
            for (int i = 0; i < 8; i++) S[i] = 0.0f;
            #pragma unroll
            for (int half8 = 0; half8 < 2; half8++) {
                int kb = g16 * 16 + half8 * 8 + brow8;
                unsigned bh[2], bl[2];
                ldm_x2(bh, scvt(&sKh[kb][0]) + bcoff);
                ldm_x2(bl, scvt(&sKl[kb][0]) + bcoff);
                float* Sd = S + half8 * 4;
                mma16816(Sd, a_hi, bh);
                mma16816(Sd, a_hi, bl);
                mma16816(Sd, a_lo, bh);
            }
            float p0 = ex2(S[0]), p1 = ex2(S[1]), p2 = ex2(S[2]), p3 = ex2(S[3]);
            float p4 = ex2(S[4]), p5 = ex2(S[5]), p6 = ex2(S[6]), p7 = ex2(S[7]);
            l0 += (p0 + p1) + (p4 + p5);   // D rows r0
            l1 += (p2 + p3) + (p6 + p7);   // D rows r0+8
            unsigned pa[4];
            pa[0] = cvt_bf16x2(p0, p1);
            pa[1] = cvt_bf16x2(p2, p3);
            pa[2] = cvt_bf16x2(p4, p5);
            pa[3] = cvt_bf16x2(p6, p7);
            int vr = g16 * 16 + vrow16;
            #pragma unroll
            for (int dh2 = 0; dh2 < 2; dh2++) {
                unsigned bvh[2], bvl[2];
                ldm_x2t(bvh, scvt(&sVh[vr][dh2 * 8]));
                ldm_x2t(bvl, scvt(&sVl[vr][dh2 * 8]));
                mma16816(o + dh2 * 4, pa, bvh);
                mma16816(o + dh2 * 4, pa, bvl);
            }
        }
        __syncthreads();
    }

    // reduce l over the 4 lanes of each row group, normalize, write
    l0 += __shfl_xor_sync(0xFFFFFFFFu, l0, 1);
    l0 += __shfl_xor_sync(0xFFFFFFFFu, l0, 2);
    l1 += __shfl_xor_sync(0xFFFFFFFFu, l1, 1);
    l1 += __shfl_xor_sync(0xFFFFFFFFu, l1, 2);
    float inv0 = 1.0f / l0, inv1 = 1.0f / l1;

    int r0c = lane >> 2;
    int cc  = (lane & 3) * 2;
    int row0 = q0 + warp * 16 + r0c;
    int row1 = row0 + 8;
    float* d0 = g_av + row0 * HID + h * DH;
    float* d1 = g_av + row1 * HID + h * DH;
    d0[cc]     = o[0] * inv0;  d0[cc + 1] = o[1] * inv0;
    d1[cc]     = o[2] * inv1;  d1[cc + 1] = o[3] * inv1;
    d0[cc + 8] = o[4] * inv0;  d0[cc + 9] = o[5] * inv0;
    d1[cc + 8] = o[6] * inv1;  d1[cc + 9] = o[7] * inv1;
}

// ---------------- 10: deterministic column mean of av ----------------
__global__ void k_colsum() {
    __shared__ float sm[256];
    int col = blockIdx.x;
    int t = threadIdx.x;
    float s = 0.0f;
    for (int r = t; r < NSEL; r += 256) s += g_av[r * HID + col];
    sm[t] = s;
    __syncthreads();
    for (int o = 128; o > 0; o >>= 1) {
        if (t < o) sm[t] += sm[t + o];
        __syncthreads();
    }
    if (t == 0) g_mav[col] = sm[0] * (1.0f / NSEL);
}

// ---------------- 11: Wo + mean-pool commuted + MLP head ----------------
__global__ void k_final(
    const float* __restrict__ Wo, const float* __restrict__ bo,
    const float* __restrict__ W1, const float* __restrict__ b1,
    const float* __restrict__ W2, const float* __restrict__ b2,
    float* __restrict__ out)
{
    __shared__ float mav[HID];
    __shared__ float pooled[HID];
    __shared__ float t1[OUTD];
    int t = threadIdx.x;  // 256 threads
    if (t < HID) mav[t] = g_mav[t];
    __syncthreads();
    if (t < HID) {
        float acc = bo[t];
        for (int d = 0; d < HID; d++) acc = fmaf(mav[d], Wo[d * HID + t], acc);
        pooled[t] = acc;
    }
    __syncthreads();
    {
        float acc = b1[t];
        for (int d = 0; d < HID; d++) acc = fmaf(pooled[d], W1[d * OUTD + t], acc);
        t1[t] = fmaxf(acc, 0.0f);
    }
    __syncthreads();
    {
        float acc = b2[t];
        for (int d = 0; d < OUTD; d++) acc = fmaf(t1[d], W2[d * OUTD + t], acc);
        out[t] = acc;
    }
}

// ---------------- launcher ----------------
extern "C" void kernel_launch(void* const* d_in, const int* in_sizes, int n_in,
                              void* d_out, int out_size)
{
    const float* x    = (const float*)d_in[0];
    const float* pos  = (const float*)d_in[1];
    const float* lig  = (const float*)d_in[2];
    const float* Wn   = (const float*)d_in[3];
    const float* bn   = (const float*)d_in[4];
    const float* Wq   = (const float*)d_in[5];
    const float* bq   = (const float*)d_in[6];
    const float* Wk   = (const float*)d_in[7];
    const float* bk   = (const float*)d_in[8];
    const float* Wv   = (const float*)d_in[9];
    const float* bv   = (const float*)d_in[10];
    const float* Wo   = (const float*)d_in[11];
    const float* bo   = (const float*)d_in[12];
    const float* W1   = (const float*)d_in[13];
    const float* b1   = (const float*)d_in[14];
    const float* W2   = (const float*)d_in[15];
    const float* b2   = (const float*)d_in[16];
    float* out = (float*)d_out;

    k_zero<<<(NBINS + NATOMS + 255) / 256, 256>>>();
    k_center_base<<<1, 1024>>>(lig, pos);
    k_neighbor<<<dim3(NATOMS / 256, 8), 256>>>(pos);
    k_scorekey<<<NATOMS / 256, 256>>>();
    k_scan<<<1, 256>>>();
    k_boundary<<<NATOMS / 256, 256>>>();
    k_flags<<<NATOMS / 256, 256>>>();
    k_bcount<<<64, 256>>>();
    k_boffsets<<<1, 32>>>();
    k_compact<<<64, 256>>>();
    k_qkv<<<NSEL / 4, 128>>>(x, Wn, bn, Wq, bq, Wk, bk, Wv, bv);
    k_attn_tc<<<dim3(NSEL / TQ, HEADS), 128>>>();
    k_colsum<<<HID, 256>>>();
    k_final<<<1, 256>>>(Wo, bo, W1, b1, W2, b2, out);
}